// round 17
// baseline (speedup 1.0000x reference)
#include <cuda_runtime.h>

#define N_ATOMS 1024
#define NBUCK   256
#define INVWB   (256.0f / 48.0f)     // buckets of width 0.1875 over [-24, 24]
#define KWIN    17                   // Δbucket ≥ 17 → Δx > 3.0 > 2.9
#define CTAS_X  16

__device__ float g_partials[2048];
__device__ unsigned int g_count = 0;

__device__ __forceinline__ float fsqrt_approx(float x) {
    float r; asm("sqrt.approx.f32 %0, %1;" : "=f"(r) : "f"(x)); return r;
}

__global__ void __launch_bounds__(256, 7)
collapse_fused(const float* __restrict__ coords,
               float* __restrict__ out,
               int nblocks, float inv_b)
{
    __shared__ float4 S[N_ATOMS];          // sorted (x,y,z,r+5e-9): 16 KB
    __shared__ int    wcnt[NBUCK][8];      // per-bucket per-warp counts -> prefixes: 8 KB
    __shared__ int    tscan[NBUCK];        // bucket totals -> inclusive scan: 1 KB
    __shared__ int    bstart[NBUCK + 1];   // bucket start offsets: 1 KB
    __shared__ float  wsum[8];
    __shared__ bool   isLast;

    const int t  = threadIdx.x;
    const int cx = blockIdx.x;             // 0..15
    const int b  = blockIdx.y;             // batch
    const int w  = t >> 5, l = t & 31;
    unsigned lmlt;
    asm("mov.u32 %0, %%lanemask_lt;" : "=r"(lmlt));

    // ---- zero this warp's counter column ----
    for (int k = l; k < NBUCK; k += 32) wcnt[k][w] = 0;

    // ---- load own 4 atoms into registers, compute r and bucket ----
    float ax[4], ay[4], az[4], ar[4];
    int   bk[4], rnk[4];
    {
        const float4* cb4 = (const float4*)(coords + (size_t)b * (3 * N_ATOMS));
        float4 f0 = cb4[3 * t], f1 = cb4[3 * t + 1], f2 = cb4[3 * t + 2];
        ax[0]=f0.x; ay[0]=f0.y; az[0]=f0.z;
        ax[1]=f0.w; ay[1]=f1.x; az[1]=f1.y;
        ax[2]=f1.z; ay[2]=f1.w; az[2]=f2.x;
        ax[3]=f2.y; ay[3]=f2.z; az[3]=f2.w;
        #pragma unroll
        for (int c = 0; c < 4; ++c) {
            // +eps/2 per endpoint so pair d2 carries the reference's +1e-8
            ar[c] = fmaf(ax[c], ax[c], fmaf(ay[c], ay[c], az[c] * az[c])) + 5e-9f;
            int bb = (int)((ax[c] + 24.0f) * INVWB);
            bk[c] = max(0, min(NBUCK - 1, bb));
        }
    }
    __syncwarp();

    // ---- deterministic ranking: round r ranks each lane's own atom r ----
    #pragma unroll
    for (int c = 0; c < 4; ++c) {
        unsigned mask = __match_any_sync(0xFFFFFFFFu, bk[c]);
        int myrank = __popc(mask & lmlt);
        int base = wcnt[bk[c]][w];
        __syncwarp();
        if (myrank == 0) wcnt[bk[c]][w] = base + __popc(mask);   // group leader
        __syncwarp();
        rnk[c] = base + myrank;
    }
    __syncthreads();

    // ---- per-bucket exclusive prefix over 8 warps (t = bucket) ----
    {
        int run = 0;
        #pragma unroll
        for (int ww = 0; ww < 8; ++ww) { int c = wcnt[t][ww]; wcnt[t][ww] = run; run += c; }
        tscan[t] = run;
    }
    __syncthreads();

    // ---- Hillis-Steele inclusive scan over 256 bucket totals ----
    for (int off = 1; off < NBUCK; off <<= 1) {
        int v = (t >= off) ? tscan[t - off] : 0;
        __syncthreads();
        tscan[t] += v;
        __syncthreads();
    }
    bstart[t + 1] = tscan[t];
    if (t == 0) bstart[0] = 0;
    __syncthreads();

    // ---- scatter own atoms into sorted smem ----
    #pragma unroll
    for (int c = 0; c < 4; ++c) {
        int pos = bstart[bk[c]] + wcnt[bk[c]][w] + rnk[c];
        S[pos] = make_float4(ax[c], ay[c], az[c], ar[c]);
    }
    __syncthreads();

    // ---- windowed pair scan: atom i = cx + 16*al (round-robin balance), 4 thr/atom ----
    const int al = t >> 2;
    const int q  = t & 3;
    const int i  = cx + CTAS_X * al;

    float4 ai = S[i];
    const float m2x = -2.f * ai.x, m2y = -2.f * ai.y, m2z = -2.f * ai.z, ri = ai.w;
    int bb = max(0, min(NBUCK - 1, (int)((ai.x + 24.0f) * INVWB)));
    const int pend = bstart[min(bb + KWIN, NBUCK)];

    float acc = 0.f;
    #pragma unroll 4
    for (int j = i + 1 + q; j < pend; j += 4) {
        float4 aj = S[j];
        float d2 = fmaf(m2x, aj.x, fmaf(m2y, aj.y, fmaf(m2z, aj.z, ri))) + aj.w;
        float v  = fmaxf(2.9f - fsqrt_approx(d2), 0.f);   // NaN guard: fmax(NaN,0)=0
        acc = fmaf(v, v, acc);
    }

    // ---- intra-CTA reduction ----
    #pragma unroll
    for (int o = 16; o > 0; o >>= 1)
        acc += __shfl_down_sync(0xFFFFFFFFu, acc, o);
    if (l == 0) wsum[w] = acc;
    __syncthreads();

    if (t == 0) {
        float s = 0.f;
        #pragma unroll
        for (int k = 0; k < 8; ++k) s += wsum[k];
        g_partials[b * gridDim.x + cx] = s;
        __threadfence();
        unsigned c = atomicAdd(&g_count, 1u);
        isLast = (c == (unsigned)(nblocks - 1));
    }
    __syncthreads();

    // ---- last CTA: fixed-order deterministic final reduce ----
    if (isLast) {
        __threadfence();
        if (t < 32) {
            float s = 0.f;
            for (int k = t; k < nblocks; k += 32)
                s += g_partials[k];
            #pragma unroll
            for (int o = 16; o > 0; o >>= 1)
                s += __shfl_down_sync(0xFFFFFFFFu, s, o);
            if (t == 0) {
                out[0] = s * inv_b;
                g_count = 0;    // reset for graph replay
            }
        }
    }
}

extern "C" void kernel_launch(void* const* d_in, const int* in_sizes, int n_in,
                              void* d_out, int out_size)
{
    const float* coords = (const float*)d_in[0];
    const int B = in_sizes[0] / (3 * N_ATOMS);   // 64

    static bool configured = false;
    if (!configured) {
        cudaFuncSetAttribute(collapse_fused,
                             cudaFuncAttributePreferredSharedMemoryCarveout, 100);
        configured = true;
    }

    dim3 grid(CTAS_X, B);                        // (16, 64) = 1024 CTAs, single kernel
    const int nblocks = CTAS_X * B;
    collapse_fused<<<grid, 256>>>(coords, (float*)d_out, nblocks, 1.0f / (float)B);
}